// round 3
// baseline (speedup 1.0000x reference)
#include <cuda_runtime.h>
#include <cstdint>

// Problem shape (fixed by reference)
constexpr int B = 16, N = 8, M = 1024, F = 512;
constexpr int F4 = F / 4;              // 128 float4 columns
constexpr int M_CHUNK = 16;            // m-rows per block
constexpr int M_CHUNKS = M / M_CHUNK;  // 64
constexpr float LOG2E = 1.4426950408889634f;

__device__ __forceinline__ float ex2_approx(float x) {
    float r;
    asm("ex2.approx.f32 %0, %1;" : "=f"(r) : "f"(x));
    return r;
}
__device__ __forceinline__ float rcp_approx(float x) {
    float r;
    asm("rcp.approx.f32 %0, %1;" : "=f"(r) : "f"(x));
    return r;
}

// ---------------------------------------------------------------------------
// One block = (b, n, m_chunk); 128 threads = one float4 f-column each.
//
// Mask dtype detection in-block: values in [0,13), so int64 (LE) => every odd
// 32-bit word is 0; OR over 256 odd words is nonzero for int32 data with
// probability 1-(1/13)^256. Words are L2-resident -> ~free.
//
// tanh(x) = 1 - 2/(exp(2x)+1)  ->  out = p - q * rcp(ex2(z*c1 + c0) + 1)
//   c1 = 2*e3*log2e, c0 = -2*e2*e3*log2e, p = e0+e1, q = 2*e1
//
// __launch_bounds__(128, 10): cap regs at ~51 so 10 CTAs (40 warps) fit per
// SM — occupancy was reg-limited to 32 warps at regs=64. More resident warps
// => more outstanding LDG.128 => higher sustained DRAM throughput.
// ---------------------------------------------------------------------------
__global__ __launch_bounds__(F4, 10)
void tanh_rt_kernel(const float4* __restrict__ z,
                    const int* __restrict__ mask32,
                    const float4* __restrict__ eta,   // [13] of (e0,e1,e2,e3)
                    float4* __restrict__ out) {
    const int f4  = threadIdx.x;           // 0..127
    const int blk = blockIdx.x;
    const int mc  = blk % M_CHUNKS;
    const int bn  = blk / M_CHUNKS;        // 0..B*N-1
    const int n   = bn % N;
    const int b   = bn / N;

    // --- in-block mask width detection (block-uniform result) ---
    unsigned acc = (unsigned)mask32[2 * f4 + 1] | (unsigned)mask32[2 * (f4 + 128) + 1];
    const int is64 = !__syncthreads_or((int)acc);

    // --- gather per-f params once into registers ---
    float c1[4], c0[4], p[4], q[4];
    #pragma unroll
    for (int j = 0; j < 4; j++) {
        const int f = f4 * 4 + j;
        const int pos = b * F + f;
        const int midx = is64 ? mask32[2 * pos] : mask32[pos];
        const float4 e = __ldg(&eta[midx]);
        const float t1 = 2.0f * e.w * LOG2E;       // 2*e3*log2e
        c1[j] = t1;
        c0[j] = -e.z * t1;                         // -2*e2*e3*log2e
        p[j]  = e.x + e.y;                         // e0 + e1
        q[j]  = 2.0f * e.y;                        // 2*e1
    }

    size_t base = ((size_t)(b * N + n) * M + (size_t)mc * M_CHUNK) * F4 + f4;

    // --- stream M_CHUNK rows: 2 float4 loads in flight per iteration ---
    #pragma unroll 2
    for (int m = 0; m < M_CHUNK; m += 2) {
        const size_t i0 = base + (size_t)m * F4;
        const size_t i1 = i0 + F4;
        float4 z0 = z[i0];
        float4 z1 = z[i1];
        float4 o0, o1;

        o0.x = fmaf(-q[0], rcp_approx(ex2_approx(fmaf(z0.x, c1[0], c0[0])) + 1.0f), p[0]);
        o0.y = fmaf(-q[1], rcp_approx(ex2_approx(fmaf(z0.y, c1[1], c0[1])) + 1.0f), p[1]);
        o0.z = fmaf(-q[2], rcp_approx(ex2_approx(fmaf(z0.z, c1[2], c0[2])) + 1.0f), p[2]);
        o0.w = fmaf(-q[3], rcp_approx(ex2_approx(fmaf(z0.w, c1[3], c0[3])) + 1.0f), p[3]);

        o1.x = fmaf(-q[0], rcp_approx(ex2_approx(fmaf(z1.x, c1[0], c0[0])) + 1.0f), p[0]);
        o1.y = fmaf(-q[1], rcp_approx(ex2_approx(fmaf(z1.y, c1[1], c0[1])) + 1.0f), p[1]);
        o1.z = fmaf(-q[2], rcp_approx(ex2_approx(fmaf(z1.z, c1[2], c0[2])) + 1.0f), p[2]);
        o1.w = fmaf(-q[3], rcp_approx(ex2_approx(fmaf(z1.w, c1[3], c0[3])) + 1.0f), p[3]);

        out[i0] = o0;
        out[i1] = o1;
    }
}

extern "C" void kernel_launch(void* const* d_in, const int* in_sizes, int n_in,
                              void* d_out, int out_size) {
    const float4* z      = (const float4*)d_in[0];
    const int*    mask32 = (const int*)d_in[1];      // int32 or int64, detected in-kernel
    const float4* eta    = (const float4*)d_in[2];   // [13,4] fp32
    float4*       out    = (float4*)d_out;

    tanh_rt_kernel<<<B * N * M_CHUNKS, F4>>>(z, mask32, eta, out);
}

// round 4
// speedup vs baseline: 1.0194x; 1.0194x over previous
#include <cuda_runtime.h>
#include <cstdint>

// Problem shape (fixed by reference)
constexpr int B = 16, N = 8, M = 1024, F = 512;
constexpr int F4 = F / 4;              // 128 float4 columns
constexpr int M_CHUNK = 16;            // m-rows per block
constexpr int M_CHUNKS = M / M_CHUNK;  // 64
constexpr float LOG2E = 1.4426950408889634f;

__device__ __forceinline__ float ex2_approx(float x) {
    float r;
    asm("ex2.approx.f32 %0, %1;" : "=f"(r) : "f"(x));
    return r;
}
__device__ __forceinline__ float rcp_approx(float x) {
    float r;
    asm("rcp.approx.f32 %0, %1;" : "=f"(r) : "f"(x));
    return r;
}

// ---------------------------------------------------------------------------
// One block = (b, n, m_chunk); 128 threads = one float4 f-column each.
//
// Mask dtype detection in-block: values in [0,13), so int64 (LE) => every odd
// 32-bit word is 0; OR over 256 odd words is nonzero for int32 data with
// probability 1-(1/13)^256. Words are L2-resident -> ~free.
//
// tanh(x) = 1 - 2/(exp(2x)+1)  ->  out = p - q * rcp(ex2(z*c1 + c0) + 1)
//   c1 = 2*e3*log2e, c0 = -2*e2*e3*log2e, p = e0+e1, q = 2*e1
//
// R3 lesson: the binding constraint is in-flight bytes per warp (MLP_p1),
// NOT occupancy. So: 4 LDG.128 batched up-front per iteration (64 B/thread
// in flight), no register cap. Streaming hints (__ldcs/__stcs) on the
// 537 MB z/out stream; mask/eta use default policy to stay L2-resident.
// ---------------------------------------------------------------------------
__global__ __launch_bounds__(F4, 8)
void tanh_rt_kernel(const float4* __restrict__ z,
                    const int* __restrict__ mask32,
                    const float4* __restrict__ eta,   // [13] of (e0,e1,e2,e3)
                    float4* __restrict__ out) {
    const int f4  = threadIdx.x;           // 0..127
    const int blk = blockIdx.x;
    const int mc  = blk % M_CHUNKS;
    const int bn  = blk / M_CHUNKS;        // 0..B*N-1
    const int n   = bn % N;
    const int b   = bn / N;

    // --- in-block mask width detection (block-uniform result) ---
    unsigned acc = (unsigned)mask32[2 * f4 + 1] | (unsigned)mask32[2 * (f4 + 128) + 1];
    const int is64 = !__syncthreads_or((int)acc);

    // --- gather per-f params once into registers ---
    float c1[4], c0[4], p[4], q[4];
    #pragma unroll
    for (int j = 0; j < 4; j++) {
        const int f = f4 * 4 + j;
        const int pos = b * F + f;
        const int midx = is64 ? mask32[2 * pos] : mask32[pos];
        const float4 e = __ldg(&eta[midx]);
        const float t1 = 2.0f * e.w * LOG2E;       // 2*e3*log2e
        c1[j] = t1;
        c0[j] = -e.z * t1;                         // -2*e2*e3*log2e
        p[j]  = e.x + e.y;                         // e0 + e1
        q[j]  = 2.0f * e.y;                        // 2*e1
    }

    size_t base = ((size_t)(b * N + n) * M + (size_t)mc * M_CHUNK) * F4 + f4;

    // --- stream M_CHUNK rows: 4 LDG.128 in flight before any compute ---
    #pragma unroll
    for (int m = 0; m < M_CHUNK; m += 4) {
        const size_t i0 = base + (size_t)m * F4;
        float4 zv[4];
        zv[0] = __ldcs(&z[i0]);
        zv[1] = __ldcs(&z[i0 + F4]);
        zv[2] = __ldcs(&z[i0 + 2 * F4]);
        zv[3] = __ldcs(&z[i0 + 3 * F4]);

        #pragma unroll
        for (int r = 0; r < 4; r++) {
            float4 o;
            o.x = fmaf(-q[0], rcp_approx(ex2_approx(fmaf(zv[r].x, c1[0], c0[0])) + 1.0f), p[0]);
            o.y = fmaf(-q[1], rcp_approx(ex2_approx(fmaf(zv[r].y, c1[1], c0[1])) + 1.0f), p[1]);
            o.z = fmaf(-q[2], rcp_approx(ex2_approx(fmaf(zv[r].z, c1[2], c0[2])) + 1.0f), p[2]);
            o.w = fmaf(-q[3], rcp_approx(ex2_approx(fmaf(zv[r].w, c1[3], c0[3])) + 1.0f), p[3]);
            __stcs(&out[i0 + (size_t)r * F4], o);
        }
    }
}

extern "C" void kernel_launch(void* const* d_in, const int* in_sizes, int n_in,
                              void* d_out, int out_size) {
    const float4* z      = (const float4*)d_in[0];
    const int*    mask32 = (const int*)d_in[1];      // int32 or int64, detected in-kernel
    const float4* eta    = (const float4*)d_in[2];   // [13,4] fp32
    float4*       out    = (float4*)d_out;

    tanh_rt_kernel<<<B * N * M_CHUNKS, F4>>>(z, mask32, eta, out);
}